// round 6
// baseline (speedup 1.0000x reference)
#include <cuda_runtime.h>
#include <cstdint>

#define N_NODES 2708
#define INS     1433
#define OUTS    64
#define M_MECH  8
#define HID     64
#define LEAK    0.2f
#define NW      85   // ceil(2708/32)
#define NCH     90   // ceil(1433/16)

typedef unsigned long long ull;

// ---------------- device scratch (no allocation allowed) ----------------
__device__ unsigned g_adj[N_NODES * NW];
__device__ float g_h[(size_t)M_MECH * N_NODES * OUTS];   // raw then FiLM'd projections
__device__ float g_h1[(size_t)N_NODES * HID];            // conditioner hidden
__device__ float g_es[M_MECH * N_NODES];
__device__ float g_ed[M_MECH * N_NODES];

// ---------------- f32x2 helpers (sm_103a packed FP32) ----------------
__device__ __forceinline__ ull pk2(float a, float b) {
    ull r; asm("mov.b64 %0, {%1, %2};" : "=l"(r) : "f"(a), "f"(b)); return r;
}
__device__ __forceinline__ float2 upk2(ull v) {
    float2 r; asm("mov.b64 {%0, %1}, %2;" : "=f"(r.x), "=f"(r.y) : "l"(v)); return r;
}
__device__ __forceinline__ ull ffma2(ull a, ull b, ull c) {
    ull d; asm("fma.rn.f32x2 %0, %1, %2, %3;" : "=l"(d) : "l"(a), "l"(b), "l"(c)); return d;
}

// ---------------- K1: bit-pack adjacency ----------------
__global__ void k_pack(const unsigned* __restrict__ adj) {
    int i = blockIdx.x;
    int lane = threadIdx.x & 31, w0 = threadIdx.x >> 5;
    for (int w = w0; w < NW; w += 4) {
        int j = w * 32 + lane;
        bool p = (j < N_NODES) && (adj[(size_t)i * N_NODES + j] != 0u);
        unsigned mask = __ballot_sync(0xFFFFFFFFu, p);
        if (lane == 0) g_adj[i * NW + w] = mask;
    }
}

// ---------------- K2: fused big GEMM, double-buffered ----------------
// C[2708, 9*64]: block gy<8 -> h_raw for mechanism gy; gy==8 -> relu(x@Wc1+bc1)
__global__ void k_gemm(const float* __restrict__ x, const float* __restrict__ W,
                       const float* __restrict__ Wc1, const float* __restrict__ bc1) {
    __shared__ float xs[2][16][68];  // transposed: xs[b][k][row]
    __shared__ float bs[2][16][64];  // bs[b][k][col]

    int n0 = blockIdx.x * 64;
    int gy = blockIdx.y;
    const float* B = (gy < M_MECH) ? (W + (size_t)gy * INS * OUTS) : Wc1;

    int t = threadIdx.x;
    int trow = t >> 4, tcol = t & 15;

    // per-thread load coordinates (4 elems each side)
    int xr[4], xk[4], bk[4], bo[4];
#pragma unroll
    for (int i = 0; i < 4; i++) {
        int e = t + 256 * i;
        xr[i] = e >> 4;  xk[i] = e & 15;
        bk[i] = e >> 6;  bo[i] = e & 63;
    }

    ull acc[8];
#pragma unroll
    for (int i = 0; i < 8; i++) acc[i] = 0ull;

    float rx[4], rb[4];
    // prologue: chunk 0
#pragma unroll
    for (int i = 0; i < 4; i++) {
        int gr = n0 + xr[i], gk = xk[i];
        rx[i] = (gr < N_NODES && gk < INS) ? x[(size_t)gr * INS + gk] : 0.f;
        rb[i] = (bk[i] < INS) ? B[(size_t)bk[i] * 64 + bo[i]] : 0.f;
    }
#pragma unroll
    for (int i = 0; i < 4; i++) {
        xs[0][xk[i]][xr[i]] = rx[i];
        bs[0][bk[i]][bo[i]] = rb[i];
    }
    __syncthreads();

    for (int c = 0; c < NCH; c++) {
        int k0n = (c + 1) * 16;
        if (c + 1 < NCH) {
#pragma unroll
            for (int i = 0; i < 4; i++) {
                int gr = n0 + xr[i], gk = k0n + xk[i];
                rx[i] = (gr < N_NODES && gk < INS) ? x[(size_t)gr * INS + gk] : 0.f;
                int gkb = k0n + bk[i];
                rb[i] = (gkb < INS) ? B[(size_t)gkb * 64 + bo[i]] : 0.f;
            }
        }
        int cb = c & 1;
#pragma unroll
        for (int kk = 0; kk < 16; kk++) {
            float4 a4 = *(const float4*)&xs[cb][kk][trow * 4];
            float4 b4 = *(const float4*)&bs[cb][kk][tcol * 4];
            ull b01 = pk2(b4.x, b4.y), b23 = pk2(b4.z, b4.w);
            float av[4] = {a4.x, a4.y, a4.z, a4.w};
#pragma unroll
            for (int i = 0; i < 4; i++) {
                ull ai = pk2(av[i], av[i]);
                acc[i * 2]     = ffma2(ai, b01, acc[i * 2]);
                acc[i * 2 + 1] = ffma2(ai, b23, acc[i * 2 + 1]);
            }
        }
        if (c + 1 < NCH) {
            int nb = cb ^ 1;
#pragma unroll
            for (int i = 0; i < 4; i++) {
                xs[nb][xk[i]][xr[i]] = rx[i];
                bs[nb][bk[i]][bo[i]] = rb[i];
            }
        }
        __syncthreads();
    }

#pragma unroll
    for (int i = 0; i < 4; i++) {
        int n = n0 + trow * 4 + i;
        if (n >= N_NODES) continue;
        float2 c01 = upk2(acc[i * 2]);
        float2 c23 = upk2(acc[i * 2 + 1]);
        int oc = tcol * 4;
        if (gy < M_MECH) {
            float4 v = make_float4(c01.x, c01.y, c23.x, c23.y);
            *(float4*)&g_h[((size_t)gy * N_NODES + n) * 64 + oc] = v;
        } else {
            float4 v = make_float4(fmaxf(c01.x + bc1[oc], 0.f),
                                   fmaxf(c01.y + bc1[oc + 1], 0.f),
                                   fmaxf(c23.x + bc1[oc + 2], 0.f),
                                   fmaxf(c23.y + bc1[oc + 3], 0.f));
            *(float4*)&g_h1[(size_t)n * 64 + oc] = v;
        }
    }
}

// ---------------- K3: conditioner out + FiLM + e_src/e_dst, fused ----------------
// warp per node
__global__ void k_cond_film(const float* __restrict__ Wc2, const float* __restrict__ bc2,
                            const float* __restrict__ a_src, const float* __restrict__ a_dst) {
    int n = blockIdx.x * 8 + (threadIdx.x >> 5);
    int lane = threadIdx.x & 31;
    if (n >= N_NODES) return;

    float v0 = g_h1[(size_t)n * 64 + lane];
    float v1 = g_h1[(size_t)n * 64 + 32 + lane];
    float s = (lane < 16) ? bc2[lane] : 0.f;
#pragma unroll
    for (int k = 0; k < 64; k++) {
        float hv = __shfl_sync(0xFFFFFFFFu, (k < 32) ? v0 : v1, k & 31);
        float w = (lane < 16) ? Wc2[k * 16 + lane] : 0.f;
        s = fmaf(hv, w, s);
    }
    // s: lane m -> gamma_m, lane 8+m -> beta_m
#pragma unroll
    for (int m = 0; m < M_MECH; m++) {
        float g = __shfl_sync(0xFFFFFFFFu, s, m);
        float b = __shfl_sync(0xFFFFFFFFu, s, m + 8);
        size_t base = ((size_t)m * N_NODES + n) * 64;
        float h0 = g_h[base + lane], h1 = g_h[base + 32 + lane];
        h0 = fmaf(g, h0, b);
        h1 = fmaf(g, h1, b);
        g_h[base + lane] = h0;
        g_h[base + 32 + lane] = h1;
        float es = h0 * a_src[m * 64 + lane] + h1 * a_src[m * 64 + 32 + lane];
        float ed = h0 * a_dst[m * 64 + lane] + h1 * a_dst[m * 64 + 32 + lane];
#pragma unroll
        for (int off = 16; off; off >>= 1) {
            es += __shfl_xor_sync(0xFFFFFFFFu, es, off);
            ed += __shfl_xor_sync(0xFFFFFFFFu, ed, off);
        }
        if (lane == 0) { g_es[m * N_NODES + n] = es; g_ed[m * N_NODES + n] = ed; }
    }
}

// ---------------- K4: masked softmax + aggregation (flash-style) ----------------
// block = (m, 64-row tile), 256 threads; adjacency read straight from L2.
// smem: ed[2720] + hs[64*64] + ws[64*65] + es[64] + maxs[64] + invs[64]
#define AR 64
#define SMEM_ATTN_WORDS (2720 + 4096 + 4160 + 64 + 64 + 64)
#define SMEM_ATTN_BYTES (SMEM_ATTN_WORDS * 4)   // 44672 < 48K

__global__ void k_attn(float* __restrict__ out) {
    extern __shared__ char smem_raw[];
    float* ed_s = (float*)smem_raw;     // [2720]
    float* hs   = ed_s + 2720;          // [64*64]
    float* ws   = hs + 4096;            // [64*65]
    float* es_s = ws + 4160;            // [64]
    float* maxs = es_s + 64;            // [64]
    float* invs = maxs + 64;            // [64]

    int m = blockIdx.y;
    int n0 = blockIdx.x * AR;
    int t = threadIdx.x, lane = t & 31, wid = t >> 5;

    for (int j = t; j < N_NODES; j += 256) ed_s[j] = g_ed[m * N_NODES + j];
    if (t < AR) {
        int n = n0 + t;
        es_s[t] = (n < N_NODES) ? g_es[m * N_NODES + n] : 0.f;
    }
    __syncthreads();

    // pass 1: max sweep, then sum sweep (warp per row)
    for (int r = wid; r < AR; r += 8) {
        int n = n0 + r;
        float es = es_s[r];
        float mx = -1e30f;
        if (n < N_NODES) {
            const unsigned* arow = g_adj + (size_t)n * NW;
            for (int k = 0; k < NW; k++) {
                unsigned word = arow[k];          // warp-uniform broadcast
                if ((word >> lane) & 1u) {
                    float v = es + ed_s[k * 32 + lane];
                    v = (v > 0.f) ? v : LEAK * v;
                    mx = fmaxf(mx, v);
                }
            }
        }
#pragma unroll
        for (int off = 16; off; off >>= 1)
            mx = fmaxf(mx, __shfl_xor_sync(0xFFFFFFFFu, mx, off));

        float sm = 0.f;
        if (n < N_NODES) {
            const unsigned* arow = g_adj + (size_t)n * NW;
            for (int k = 0; k < NW; k++) {
                unsigned word = arow[k];
                if ((word >> lane) & 1u) {
                    float v = es + ed_s[k * 32 + lane];
                    v = (v > 0.f) ? v : LEAK * v;
                    sm += __expf(v - mx);
                }
            }
        }
#pragma unroll
        for (int off = 16; off; off >>= 1)
            sm += __shfl_xor_sync(0xFFFFFFFFu, sm, off);

        if (lane == 0) {
            maxs[r] = mx;
            invs[r] = (sm > 0.f) ? 1.f / sm : 0.f;
        }
    }
    __syncthreads();

    // pass 2: 2 rows x 8 feats per thread
    int rg = t >> 3, og = t & 7, ob = og * 8;
    ull acc0[4], acc1[4];
#pragma unroll
    for (int i = 0; i < 4; i++) { acc0[i] = 0ull; acc1[i] = 0ull; }

    for (int jt = 0; jt < N_NODES; jt += 64) {
        const float* hsrc = g_h + ((size_t)m * N_NODES + jt) * 64;
        int jrem = N_NODES - jt;
        // stage h tile [64 x 64]
#pragma unroll
        for (int i = 0; i < 4; i++) {
            int e4 = t + 256 * i;
            int jj = e4 >> 4, oc = (e4 & 15) * 4;
            float4 v = (jj < jrem) ? *(const float4*)&hsrc[(size_t)jj * 64 + oc]
                                   : make_float4(0.f, 0.f, 0.f, 0.f);
            *(float4*)&hs[jj * 64 + oc] = v;
        }
        // weights [64 rows x 64 j]
#pragma unroll
        for (int i = 0; i < 16; i++) {
            int e = t + 256 * i;
            int rr = e >> 6, jl = e & 63;
            int j = jt + jl, n = n0 + rr;
            float w = 0.f;
            if (j < N_NODES && n < N_NODES) {
                unsigned word = g_adj[(size_t)n * NW + (j >> 5)];  // warp-uniform
                if ((word >> (j & 31)) & 1u) {
                    float v = es_s[rr] + ed_s[j];
                    v = (v > 0.f) ? v : LEAK * v;
                    w = __expf(v - maxs[rr]);
                }
            }
            ws[rr * 65 + jl] = w;
        }
        __syncthreads();
#pragma unroll 8
        for (int jj = 0; jj < 64; jj++) {
            float w0 = ws[rg * 65 + jj];
            float w1 = ws[(rg + 32) * 65 + jj];
            ull w02 = pk2(w0, w0), w12 = pk2(w1, w1);
            const ull* hp = (const ull*)&hs[jj * 64 + ob];
            ulonglong2 p0 = *(const ulonglong2*)(hp);
            ulonglong2 p1 = *(const ulonglong2*)(hp + 2);
            acc0[0] = ffma2(w02, p0.x, acc0[0]);
            acc0[1] = ffma2(w02, p0.y, acc0[1]);
            acc0[2] = ffma2(w02, p1.x, acc0[2]);
            acc0[3] = ffma2(w02, p1.y, acc0[3]);
            acc1[0] = ffma2(w12, p0.x, acc1[0]);
            acc1[1] = ffma2(w12, p0.y, acc1[1]);
            acc1[2] = ffma2(w12, p1.x, acc1[2]);
            acc1[3] = ffma2(w12, p1.y, acc1[3]);
        }
        __syncthreads();
    }

#pragma unroll
    for (int half = 0; half < 2; half++) {
        int r = rg + half * 32;
        int n = n0 + r;
        if (n >= N_NODES) continue;
        float inv = invs[r];
        ull* acc = half ? acc1 : acc0;
        float o8[8];
#pragma unroll
        for (int i = 0; i < 4; i++) {
            float2 f = upk2(acc[i]);
            o8[2 * i]     = f.x * inv;
            o8[2 * i + 1] = f.y * inv;
        }
        float* dst = out + (size_t)n * (M_MECH * OUTS) + m * 64 + ob;
        *(float4*)(dst)     = make_float4(o8[0], o8[1], o8[2], o8[3]);
        *(float4*)(dst + 4) = make_float4(o8[4], o8[5], o8[6], o8[7]);
    }
}

// ---------------- launch ----------------
extern "C" void kernel_launch(void* const* d_in, const int* in_sizes, int n_in,
                              void* d_out, int out_size) {
    const float*    x     = (const float*)d_in[0];
    const unsigned* adj   = (const unsigned*)d_in[1];
    const float*    W     = (const float*)d_in[2];
    const float*    a_src = (const float*)d_in[3];
    const float*    a_dst = (const float*)d_in[4];
    const float*    Wc1   = (const float*)d_in[5];
    const float*    bc1   = (const float*)d_in[6];
    const float*    Wc2   = (const float*)d_in[7];
    const float*    bc2   = (const float*)d_in[8];
    float* out = (float*)d_out;

    k_pack<<<N_NODES, 128>>>(adj);
    k_gemm<<<dim3(43, 9), 256>>>(x, W, Wc1, bc1);
    k_cond_film<<<339, 256>>>(Wc2, bc2, a_src, a_dst);
    k_attn<<<dim3((N_NODES + AR - 1) / AR, M_MECH), 256, SMEM_ATTN_BYTES>>>(out);
}

// round 8
// speedup vs baseline: 1.7359x; 1.7359x over previous
#include <cuda_runtime.h>
#include <cstdint>

#define N_NODES 2708
#define INS     1433
#define OUTS    64
#define M_MECH  8
#define HID     64
#define LEAK    0.2f
#define NW      85   // ceil(2708/32)
#define NCH     90   // ceil(1433/16)

typedef unsigned long long ull;

// ---------------- device scratch (no allocation allowed) ----------------
__device__ unsigned g_adj[N_NODES * NW];
__device__ float g_h[(size_t)M_MECH * N_NODES * OUTS];   // raw then FiLM'd projections
__device__ float g_h1[(size_t)N_NODES * HID];            // conditioner hidden
__device__ float g_es[M_MECH * N_NODES];
__device__ float g_ed[M_MECH * N_NODES];

// ---------------- f32x2 helpers (sm_103a packed FP32) ----------------
__device__ __forceinline__ ull pk2(float a, float b) {
    ull r; asm("mov.b64 %0, {%1, %2};" : "=l"(r) : "f"(a), "f"(b)); return r;
}
__device__ __forceinline__ float2 upk2(ull v) {
    float2 r; asm("mov.b64 {%0, %1}, %2;" : "=f"(r.x), "=f"(r.y) : "l"(v)); return r;
}
__device__ __forceinline__ ull ffma2(ull a, ull b, ull c) {
    ull d; asm("fma.rn.f32x2 %0, %1, %2, %3;" : "=l"(d) : "l"(a), "l"(b), "l"(c)); return d;
}

// ---------------- K1: bit-pack adjacency ----------------
__global__ void k_pack(const unsigned* __restrict__ adj) {
    int i = blockIdx.x;
    int lane = threadIdx.x & 31, w0 = threadIdx.x >> 5;
    for (int w = w0; w < NW; w += 4) {
        int j = w * 32 + lane;
        bool p = (j < N_NODES) && (adj[(size_t)i * N_NODES + j] != 0u);
        unsigned mask = __ballot_sync(0xFFFFFFFFu, p);
        if (lane == 0) g_adj[i * NW + w] = mask;
    }
}

// ---------------- K2: fused big GEMM, double-buffered ----------------
__global__ void k_gemm(const float* __restrict__ x, const float* __restrict__ W,
                       const float* __restrict__ Wc1, const float* __restrict__ bc1) {
    __shared__ float xs[2][16][68];
    __shared__ float bs[2][16][64];

    int n0 = blockIdx.x * 64;
    int gy = blockIdx.y;
    const float* B = (gy < M_MECH) ? (W + (size_t)gy * INS * OUTS) : Wc1;

    int t = threadIdx.x;
    int trow = t >> 4, tcol = t & 15;

    int xr[4], xk[4], bk[4], bo[4];
#pragma unroll
    for (int i = 0; i < 4; i++) {
        int e = t + 256 * i;
        xr[i] = e >> 4;  xk[i] = e & 15;
        bk[i] = e >> 6;  bo[i] = e & 63;
    }

    ull acc[8];
#pragma unroll
    for (int i = 0; i < 8; i++) acc[i] = 0ull;

    float rx[4], rb[4];
#pragma unroll
    for (int i = 0; i < 4; i++) {
        int gr = n0 + xr[i], gk = xk[i];
        rx[i] = (gr < N_NODES && gk < INS) ? x[(size_t)gr * INS + gk] : 0.f;
        rb[i] = (bk[i] < INS) ? B[(size_t)bk[i] * 64 + bo[i]] : 0.f;
    }
#pragma unroll
    for (int i = 0; i < 4; i++) {
        xs[0][xk[i]][xr[i]] = rx[i];
        bs[0][bk[i]][bo[i]] = rb[i];
    }
    __syncthreads();

    for (int c = 0; c < NCH; c++) {
        int k0n = (c + 1) * 16;
        if (c + 1 < NCH) {
#pragma unroll
            for (int i = 0; i < 4; i++) {
                int gr = n0 + xr[i], gk = k0n + xk[i];
                rx[i] = (gr < N_NODES && gk < INS) ? x[(size_t)gr * INS + gk] : 0.f;
                int gkb = k0n + bk[i];
                rb[i] = (gkb < INS) ? B[(size_t)gkb * 64 + bo[i]] : 0.f;
            }
        }
        int cb = c & 1;
#pragma unroll
        for (int kk = 0; kk < 16; kk++) {
            float4 a4 = *(const float4*)&xs[cb][kk][trow * 4];
            float4 b4 = *(const float4*)&bs[cb][kk][tcol * 4];
            ull b01 = pk2(b4.x, b4.y), b23 = pk2(b4.z, b4.w);
            float av[4] = {a4.x, a4.y, a4.z, a4.w};
#pragma unroll
            for (int i = 0; i < 4; i++) {
                ull ai = pk2(av[i], av[i]);
                acc[i * 2]     = ffma2(ai, b01, acc[i * 2]);
                acc[i * 2 + 1] = ffma2(ai, b23, acc[i * 2 + 1]);
            }
        }
        if (c + 1 < NCH) {
            int nb = cb ^ 1;
#pragma unroll
            for (int i = 0; i < 4; i++) {
                xs[nb][xk[i]][xr[i]] = rx[i];
                bs[nb][bk[i]][bo[i]] = rb[i];
            }
        }
        __syncthreads();
    }

#pragma unroll
    for (int i = 0; i < 4; i++) {
        int n = n0 + trow * 4 + i;
        if (n >= N_NODES) continue;
        float2 c01 = upk2(acc[i * 2]);
        float2 c23 = upk2(acc[i * 2 + 1]);
        int oc = tcol * 4;
        if (gy < M_MECH) {
            float4 v = make_float4(c01.x, c01.y, c23.x, c23.y);
            *(float4*)&g_h[((size_t)gy * N_NODES + n) * 64 + oc] = v;
        } else {
            float4 v = make_float4(fmaxf(c01.x + bc1[oc], 0.f),
                                   fmaxf(c01.y + bc1[oc + 1], 0.f),
                                   fmaxf(c23.x + bc1[oc + 2], 0.f),
                                   fmaxf(c23.y + bc1[oc + 3], 0.f));
            *(float4*)&g_h1[(size_t)n * 64 + oc] = v;
        }
    }
}

// ---------------- K3: conditioner out + FiLM + e_src/e_dst, fused ----------------
__global__ void k_cond_film(const float* __restrict__ Wc2, const float* __restrict__ bc2,
                            const float* __restrict__ a_src, const float* __restrict__ a_dst) {
    int n = blockIdx.x * 8 + (threadIdx.x >> 5);
    int lane = threadIdx.x & 31;
    if (n >= N_NODES) return;

    float v0 = g_h1[(size_t)n * 64 + lane];
    float v1 = g_h1[(size_t)n * 64 + 32 + lane];
    float s = (lane < 16) ? bc2[lane] : 0.f;
#pragma unroll
    for (int k = 0; k < 64; k++) {
        float hv = __shfl_sync(0xFFFFFFFFu, (k < 32) ? v0 : v1, k & 31);
        float w = (lane < 16) ? Wc2[k * 16 + lane] : 0.f;
        s = fmaf(hv, w, s);
    }
#pragma unroll
    for (int m = 0; m < M_MECH; m++) {
        float g = __shfl_sync(0xFFFFFFFFu, s, m);
        float b = __shfl_sync(0xFFFFFFFFu, s, m + 8);
        size_t base = ((size_t)m * N_NODES + n) * 64;
        float h0 = g_h[base + lane], h1 = g_h[base + 32 + lane];
        h0 = fmaf(g, h0, b);
        h1 = fmaf(g, h1, b);
        g_h[base + lane] = h0;
        g_h[base + 32 + lane] = h1;
        float es = h0 * a_src[m * 64 + lane] + h1 * a_src[m * 64 + 32 + lane];
        float ed = h0 * a_dst[m * 64 + lane] + h1 * a_dst[m * 64 + 32 + lane];
#pragma unroll
        for (int off = 16; off; off >>= 1) {
            es += __shfl_xor_sync(0xFFFFFFFFu, es, off);
            ed += __shfl_xor_sync(0xFFFFFFFFu, ed, off);
        }
        if (lane == 0) { g_es[m * N_NODES + n] = es; g_ed[m * N_NODES + n] = ed; }
    }
}

// ---------------- K4: masked softmax + aggregation ----------------
// block = (m, 64-row tile), 128 threads in two 64-thread j-groups.
// Each thread: 8 rows x 8 feats register tile (32 f32x2 accumulators).
#define AR   64
#define TJ   64
#define WST  72   // wsT[jj][row] stride (words), 16B-aligned rows
#define HST  72   // hs[jj][feat] stride

__global__ void __launch_bounds__(128, 4) k_attn(float* __restrict__ out) {
    __shared__ float ed_s[N_NODES];
    __shared__ float es_s[AR];
    __shared__ float maxs[AR];
    __shared__ float invs[AR];
    __shared__ float hs[TJ * HST];     // h tile: [jj][feat]
    __shared__ float wsT[TJ * WST];    // weights transposed: [jj][row]; reused as combine buf

    int m = blockIdx.y;
    int n0 = blockIdx.x * AR;
    int t = threadIdx.x, lane = t & 31, wid = t >> 5;
    int h = t >> 6, tl = t & 63;       // j-group, index within group
    int rg = tl >> 3, fg = tl & 7;     // rows rg*8..rg*8+7, feats fg*8..fg*8+7

    for (int j = t; j < N_NODES; j += 128) ed_s[j] = g_ed[m * N_NODES + j];
    if (t < AR) {
        int n = n0 + t;
        es_s[t] = (n < N_NODES) ? g_es[m * N_NODES + n] : 0.f;
    }
    __syncthreads();

    // ---- pass 1: max sweep then sum sweep (warp per row) ----
    for (int r = wid; r < AR; r += 4) {
        int n = n0 + r;
        float es = es_s[r];
        float mx = -1e30f;
        if (n < N_NODES) {
            const unsigned* arow = g_adj + (size_t)n * NW;
            for (int k = 0; k < NW; k++) {
                unsigned word = arow[k];
                if ((word >> lane) & 1u) {
                    float v = es + ed_s[k * 32 + lane];
                    v = (v > 0.f) ? v : LEAK * v;
                    mx = fmaxf(mx, v);
                }
            }
        }
#pragma unroll
        for (int off = 16; off; off >>= 1)
            mx = fmaxf(mx, __shfl_xor_sync(0xFFFFFFFFu, mx, off));

        float sm = 0.f;
        if (n < N_NODES) {
            const unsigned* arow = g_adj + (size_t)n * NW;
            for (int k = 0; k < NW; k++) {
                unsigned word = arow[k];
                if ((word >> lane) & 1u) {
                    float v = es + ed_s[k * 32 + lane];
                    v = (v > 0.f) ? v : LEAK * v;
                    sm += __expf(v - mx);
                }
            }
        }
#pragma unroll
        for (int off = 16; off; off >>= 1)
            sm += __shfl_xor_sync(0xFFFFFFFFu, sm, off);

        if (lane == 0) {
            maxs[r] = mx;
            invs[r] = (sm > 0.f) ? 1.f / sm : 0.f;
        }
    }
    __syncthreads();

    // ---- pass 2: register-tiled aggregation ----
    ull acc[8][4];
#pragma unroll
    for (int i = 0; i < 8; i++)
#pragma unroll
        for (int c = 0; c < 4; c++) acc[i][c] = 0ull;

    for (int jt = 0; jt < N_NODES; jt += TJ) {
        const float* hsrc = g_h + ((size_t)m * N_NODES + jt) * 64;
        int jrem = N_NODES - jt;
        // stage h tile [TJ x 64] -> hs[jj][feat]
#pragma unroll
        for (int i = 0; i < 8; i++) {
            int e4 = t + 128 * i;
            int jj = e4 >> 4, oc = (e4 & 15) * 4;
            float4 v = (jj < jrem) ? *(const float4*)&hsrc[(size_t)jj * 64 + oc]
                                   : make_float4(0.f, 0.f, 0.f, 0.f);
            *(float4*)&hs[jj * HST + oc] = v;
        }
        // weights -> wsT[jl][rr] (transposed)
#pragma unroll
        for (int i = 0; i < 32; i++) {
            int e = t + 128 * i;
            int rr = e & 63, jl = e >> 6;
            int j = jt + jl, n = n0 + rr;
            float w = 0.f;
            if (j < N_NODES && n < N_NODES) {
                unsigned word = g_adj[(size_t)n * NW + (j >> 5)];
                if ((word >> (j & 31)) & 1u) {
                    float v = es_s[rr] + ed_s[j];
                    v = (v > 0.f) ? v : LEAK * v;
                    w = __expf(v - maxs[rr]);
                }
            }
            wsT[jl * WST + rr] = w;
        }
        __syncthreads();

        int jj0 = h * 32;
#pragma unroll 4
        for (int q = 0; q < 32; q++) {
            int jj = jj0 + q;
            // 8 row-weights (2 LDS.128)
            float4 wa = *(const float4*)&wsT[jj * WST + rg * 8];
            float4 wb = *(const float4*)&wsT[jj * WST + rg * 8 + 4];
            // 8 feats (2 LDS.128 = 4 f32x2)
            const ull* hp = (const ull*)&hs[jj * HST + fg * 8];
            ulonglong2 p0 = *(const ulonglong2*)(hp);
            ulonglong2 p1 = *(const ulonglong2*)(hp + 2);
            float wv[8] = {wa.x, wa.y, wa.z, wa.w, wb.x, wb.y, wb.z, wb.w};
#pragma unroll
            for (int i = 0; i < 8; i++) {
                ull w2 = pk2(wv[i], wv[i]);
                acc[i][0] = ffma2(w2, p0.x, acc[i][0]);
                acc[i][1] = ffma2(w2, p0.y, acc[i][1]);
                acc[i][2] = ffma2(w2, p1.x, acc[i][2]);
                acc[i][3] = ffma2(w2, p1.y, acc[i][3]);
            }
        }
        __syncthreads();
    }

    // ---- combine the two j-groups (reuse wsT as buffer) ----
    float* buf = wsT;   // need 64*66 = 4224 words <= 64*72
    if (h == 1) {
#pragma unroll
        for (int i = 0; i < 8; i++)
#pragma unroll
            for (int c = 0; c < 4; c++) {
                float2 f = upk2(acc[i][c]);
                buf[tl * 66 + i * 8 + c * 2]     = f.x;
                buf[tl * 66 + i * 8 + c * 2 + 1] = f.y;
            }
    }
    __syncthreads();
    if (h == 0) {
#pragma unroll
        for (int i = 0; i < 8; i++) {
            int r = rg * 8 + i;
            int n = n0 + r;
            if (n >= N_NODES) continue;
            float inv = invs[r];
            float o8[8];
#pragma unroll
            for (int c = 0; c < 4; c++) {
                float2 f = upk2(acc[i][c]);
                o8[c * 2]     = (f.x + buf[tl * 66 + i * 8 + c * 2])     * inv;
                o8[c * 2 + 1] = (f.y + buf[tl * 66 + i * 8 + c * 2 + 1]) * inv;
            }
            float* dst = out + (size_t)n * (M_MECH * OUTS) + m * 64 + fg * 8;
            *(float4*)(dst)     = make_float4(o8[0], o8[1], o8[2], o8[3]);
            *(float4*)(dst + 4) = make_float4(o8[4], o8[5], o8[6], o8[7]);
        }
    }
}

// ---------------- launch ----------------
extern "C" void kernel_launch(void* const* d_in, const int* in_sizes, int n_in,
                              void* d_out, int out_size) {
    const float*    x     = (const float*)d_in[0];
    const unsigned* adj   = (const unsigned*)d_in[1];
    const float*    W     = (const float*)d_in[2];
    const float*    a_src = (const float*)d_in[3];
    const float*    a_dst = (const float*)d_in[4];
    const float*    Wc1   = (const float*)d_in[5];
    const float*    bc1   = (const float*)d_in[6];
    const float*    Wc2   = (const float*)d_in[7];
    const float*    bc2   = (const float*)d_in[8];
    float* out = (float*)d_out;

    k_pack<<<N_NODES, 128>>>(adj);
    k_gemm<<<dim3(43, 9), 256>>>(x, W, Wc1, bc1);
    k_cond_film<<<339, 256>>>(Wc2, bc2, a_src, a_dst);
    k_attn<<<dim3((N_NODES + AR - 1) / AR, M_MECH), 128>>>(out);
}

// round 9
// speedup vs baseline: 2.2379x; 1.2892x over previous
#include <cuda_runtime.h>
#include <cstdint>

#define N_NODES 2708
#define INS     1433
#define OUTS    64
#define M_MECH  8
#define HID     64
#define LEAK    0.2f
#define NW      85   // ceil(2708/32)
#define NCH     90   // ceil(1433/16)

typedef unsigned long long ull;

// ---------------- device scratch (no allocation allowed) ----------------
__device__ unsigned g_adj[N_NODES * NW];
__device__ float g_h[(size_t)M_MECH * N_NODES * OUTS];   // raw then FiLM'd projections
__device__ float g_h1[(size_t)N_NODES * HID];            // conditioner hidden
__device__ float g_es[M_MECH * N_NODES];
__device__ float g_ed[M_MECH * N_NODES];

// ---------------- f32x2 helpers (sm_103a packed FP32) ----------------
__device__ __forceinline__ ull pk2(float a, float b) {
    ull r; asm("mov.b64 %0, {%1, %2};" : "=l"(r) : "f"(a), "f"(b)); return r;
}
__device__ __forceinline__ float2 upk2(ull v) {
    float2 r; asm("mov.b64 {%0, %1}, %2;" : "=f"(r.x), "=f"(r.y) : "l"(v)); return r;
}
__device__ __forceinline__ ull ffma2(ull a, ull b, ull c) {
    ull d; asm("fma.rn.f32x2 %0, %1, %2, %3;" : "=l"(d) : "l"(a), "l"(b), "l"(c)); return d;
}

// ---------------- K1: bit-pack adjacency ----------------
__global__ void k_pack(const unsigned* __restrict__ adj) {
    int i = blockIdx.x;
    int lane = threadIdx.x & 31, w0 = threadIdx.x >> 5;
    for (int w = w0; w < NW; w += 4) {
        int j = w * 32 + lane;
        bool p = (j < N_NODES) && (adj[(size_t)i * N_NODES + j] != 0u);
        unsigned mask = __ballot_sync(0xFFFFFFFFu, p);
        if (lane == 0) g_adj[i * NW + w] = mask;
    }
}

// ---------------- K2: fused big GEMM, double-buffered ----------------
__global__ void k_gemm(const float* __restrict__ x, const float* __restrict__ W,
                       const float* __restrict__ Wc1, const float* __restrict__ bc1) {
    __shared__ float xs[2][16][68];
    __shared__ float bs[2][16][64];

    int n0 = blockIdx.x * 64;
    int gy = blockIdx.y;
    const float* B = (gy < M_MECH) ? (W + (size_t)gy * INS * OUTS) : Wc1;

    int t = threadIdx.x;
    int trow = t >> 4, tcol = t & 15;

    int xr[4], xk[4], bk[4], bo[4];
#pragma unroll
    for (int i = 0; i < 4; i++) {
        int e = t + 256 * i;
        xr[i] = e >> 4;  xk[i] = e & 15;
        bk[i] = e >> 6;  bo[i] = e & 63;
    }

    ull acc[8];
#pragma unroll
    for (int i = 0; i < 8; i++) acc[i] = 0ull;

    float rx[4], rb[4];
#pragma unroll
    for (int i = 0; i < 4; i++) {
        int gr = n0 + xr[i], gk = xk[i];
        rx[i] = (gr < N_NODES && gk < INS) ? x[(size_t)gr * INS + gk] : 0.f;
        rb[i] = (bk[i] < INS) ? B[(size_t)bk[i] * 64 + bo[i]] : 0.f;
    }
#pragma unroll
    for (int i = 0; i < 4; i++) {
        xs[0][xk[i]][xr[i]] = rx[i];
        bs[0][bk[i]][bo[i]] = rb[i];
    }
    __syncthreads();

    for (int c = 0; c < NCH; c++) {
        int k0n = (c + 1) * 16;
        if (c + 1 < NCH) {
#pragma unroll
            for (int i = 0; i < 4; i++) {
                int gr = n0 + xr[i], gk = k0n + xk[i];
                rx[i] = (gr < N_NODES && gk < INS) ? x[(size_t)gr * INS + gk] : 0.f;
                int gkb = k0n + bk[i];
                rb[i] = (gkb < INS) ? B[(size_t)gkb * 64 + bo[i]] : 0.f;
            }
        }
        int cb = c & 1;
#pragma unroll
        for (int kk = 0; kk < 16; kk++) {
            float4 a4 = *(const float4*)&xs[cb][kk][trow * 4];
            float4 b4 = *(const float4*)&bs[cb][kk][tcol * 4];
            ull b01 = pk2(b4.x, b4.y), b23 = pk2(b4.z, b4.w);
            float av[4] = {a4.x, a4.y, a4.z, a4.w};
#pragma unroll
            for (int i = 0; i < 4; i++) {
                ull ai = pk2(av[i], av[i]);
                acc[i * 2]     = ffma2(ai, b01, acc[i * 2]);
                acc[i * 2 + 1] = ffma2(ai, b23, acc[i * 2 + 1]);
            }
        }
        if (c + 1 < NCH) {
            int nb = cb ^ 1;
#pragma unroll
            for (int i = 0; i < 4; i++) {
                xs[nb][xk[i]][xr[i]] = rx[i];
                bs[nb][bk[i]][bo[i]] = rb[i];
            }
        }
        __syncthreads();
    }

#pragma unroll
    for (int i = 0; i < 4; i++) {
        int n = n0 + trow * 4 + i;
        if (n >= N_NODES) continue;
        float2 c01 = upk2(acc[i * 2]);
        float2 c23 = upk2(acc[i * 2 + 1]);
        int oc = tcol * 4;
        if (gy < M_MECH) {
            float4 v = make_float4(c01.x, c01.y, c23.x, c23.y);
            *(float4*)&g_h[((size_t)gy * N_NODES + n) * 64 + oc] = v;
        } else {
            float4 v = make_float4(fmaxf(c01.x + bc1[oc], 0.f),
                                   fmaxf(c01.y + bc1[oc + 1], 0.f),
                                   fmaxf(c23.x + bc1[oc + 2], 0.f),
                                   fmaxf(c23.y + bc1[oc + 3], 0.f));
            *(float4*)&g_h1[(size_t)n * 64 + oc] = v;
        }
    }
}

// ---------------- K3: conditioner out + FiLM + e_src/e_dst, fused ----------------
__global__ void k_cond_film(const float* __restrict__ Wc2, const float* __restrict__ bc2,
                            const float* __restrict__ a_src, const float* __restrict__ a_dst) {
    int n = blockIdx.x * 8 + (threadIdx.x >> 5);
    int lane = threadIdx.x & 31;
    if (n >= N_NODES) return;

    float v0 = g_h1[(size_t)n * 64 + lane];
    float v1 = g_h1[(size_t)n * 64 + 32 + lane];
    float s = (lane < 16) ? bc2[lane] : 0.f;
#pragma unroll
    for (int k = 0; k < 64; k++) {
        float hv = __shfl_sync(0xFFFFFFFFu, (k < 32) ? v0 : v1, k & 31);
        float w = (lane < 16) ? Wc2[k * 16 + lane] : 0.f;
        s = fmaf(hv, w, s);
    }
#pragma unroll
    for (int m = 0; m < M_MECH; m++) {
        float g = __shfl_sync(0xFFFFFFFFu, s, m);
        float b = __shfl_sync(0xFFFFFFFFu, s, m + 8);
        size_t base = ((size_t)m * N_NODES + n) * 64;
        float h0 = g_h[base + lane], h1 = g_h[base + 32 + lane];
        h0 = fmaf(g, h0, b);
        h1 = fmaf(g, h1, b);
        g_h[base + lane] = h0;
        g_h[base + 32 + lane] = h1;
        float es = h0 * a_src[m * 64 + lane] + h1 * a_src[m * 64 + 32 + lane];
        float ed = h0 * a_dst[m * 64 + lane] + h1 * a_dst[m * 64 + 32 + lane];
#pragma unroll
        for (int off = 16; off; off >>= 1) {
            es += __shfl_xor_sync(0xFFFFFFFFu, es, off);
            ed += __shfl_xor_sync(0xFFFFFFFFu, ed, off);
        }
        if (lane == 0) { g_es[m * N_NODES + n] = es; g_ed[m * N_NODES + n] = ed; }
    }
}

// ---------------- K4: masked softmax + aggregation ----------------
// block = (m, 64-row tile), 256 threads. Thread tile: 4 rows x 4 feats
// (16 f32x2 accumulators = 32 regs), every thread sweeps all 64 jj per tile.
// No j-split -> no combine. 3 blocks/SM resident -> whole grid in one wave.
#define AR   64
#define TJ   64
#define WST  72   // wsT[jj][row] stride (words)
#define HST  72   // hs[jj][feat] stride

__global__ void __launch_bounds__(256, 3) k_attn(float* __restrict__ out) {
    __shared__ float ed_s[N_NODES];
    __shared__ float es_s[AR];
    __shared__ float maxs[AR];
    __shared__ float invs[AR];
    __shared__ float hs[TJ * HST];     // h tile: [jj][feat]
    __shared__ float wsT[TJ * WST];    // weights transposed: [jj][row]

    int m = blockIdx.y;
    int n0 = blockIdx.x * AR;
    int t = threadIdx.x, lane = t & 31, wid = t >> 5;
    int rg = t >> 4, fg = t & 15;      // rows rg*4.., feats fg*4..

    for (int j = t; j < N_NODES; j += 256) ed_s[j] = g_ed[m * N_NODES + j];
    if (t < AR) {
        int n = n0 + t;
        es_s[t] = (n < N_NODES) ? g_es[m * N_NODES + n] : 0.f;
    }
    __syncthreads();

    // ---- pass 1: max sweep then sum sweep (warp per row, 8 warps) ----
    for (int r = wid; r < AR; r += 8) {
        int n = n0 + r;
        float es = es_s[r];
        float mx = -1e30f;
        if (n < N_NODES) {
            const unsigned* arow = g_adj + (size_t)n * NW;
            for (int k = 0; k < NW; k++) {
                unsigned word = arow[k];      // warp-uniform broadcast
                if ((word >> lane) & 1u) {
                    float v = es + ed_s[k * 32 + lane];
                    v = (v > 0.f) ? v : LEAK * v;
                    mx = fmaxf(mx, v);
                }
            }
        }
#pragma unroll
        for (int off = 16; off; off >>= 1)
            mx = fmaxf(mx, __shfl_xor_sync(0xFFFFFFFFu, mx, off));

        float sm = 0.f;
        if (n < N_NODES) {
            const unsigned* arow = g_adj + (size_t)n * NW;
            for (int k = 0; k < NW; k++) {
                unsigned word = arow[k];
                if ((word >> lane) & 1u) {
                    float v = es + ed_s[k * 32 + lane];
                    v = (v > 0.f) ? v : LEAK * v;
                    sm += __expf(v - mx);
                }
            }
        }
#pragma unroll
        for (int off = 16; off; off >>= 1)
            sm += __shfl_xor_sync(0xFFFFFFFFu, sm, off);

        if (lane == 0) {
            maxs[r] = mx;
            invs[r] = (sm > 0.f) ? 1.f / sm : 0.f;
        }
    }
    __syncthreads();

    // ---- pass 2: register-tiled aggregation, 4 rows x 4 feats per thread ----
    ull acc[4][2];
#pragma unroll
    for (int i = 0; i < 4; i++) { acc[i][0] = 0ull; acc[i][1] = 0ull; }

    for (int jt = 0; jt < N_NODES; jt += TJ) {
        const float* hsrc = g_h + ((size_t)m * N_NODES + jt) * 64;
        int jrem = N_NODES - jt;
        // stage h tile [TJ x 64] -> hs[jj][feat] (4 float4 per thread)
#pragma unroll
        for (int i = 0; i < 4; i++) {
            int e4 = t + 256 * i;
            int jj = e4 >> 4, oc = (e4 & 15) * 4;
            float4 v = (jj < jrem) ? *(const float4*)&hsrc[(size_t)jj * 64 + oc]
                                   : make_float4(0.f, 0.f, 0.f, 0.f);
            *(float4*)&hs[jj * HST + oc] = v;
        }
        // weights -> wsT[jl][rr] (transposed), 16 entries per thread
#pragma unroll
        for (int i = 0; i < 16; i++) {
            int e = t + 256 * i;
            int rr = e & 63, jl = e >> 6;
            int j = jt + jl, n = n0 + rr;
            float w = 0.f;
            if (j < N_NODES && n < N_NODES) {
                unsigned word = g_adj[(size_t)n * NW + (j >> 5)];  // warp-uniform
                if ((word >> (j & 31)) & 1u) {
                    float v = es_s[rr] + ed_s[j];
                    v = (v > 0.f) ? v : LEAK * v;
                    w = __expf(v - maxs[rr]);
                }
            }
            wsT[jl * WST + rr] = w;
        }
        __syncthreads();

        const float* wp = &wsT[rg * 4];
        const ull*   hp = (const ull*)&hs[fg * 4];
#pragma unroll 8
        for (int jj = 0; jj < TJ; jj++) {
            float4 w4 = *(const float4*)(wp + jj * WST);
            ulonglong2 p = *(const ulonglong2*)(hp + jj * (HST / 2));
            ull w0 = pk2(w4.x, w4.x);
            ull w1 = pk2(w4.y, w4.y);
            ull w2 = pk2(w4.z, w4.z);
            ull w3 = pk2(w4.w, w4.w);
            acc[0][0] = ffma2(w0, p.x, acc[0][0]);
            acc[0][1] = ffma2(w0, p.y, acc[0][1]);
            acc[1][0] = ffma2(w1, p.x, acc[1][0]);
            acc[1][1] = ffma2(w1, p.y, acc[1][1]);
            acc[2][0] = ffma2(w2, p.x, acc[2][0]);
            acc[2][1] = ffma2(w2, p.y, acc[2][1]);
            acc[3][0] = ffma2(w3, p.x, acc[3][0]);
            acc[3][1] = ffma2(w3, p.y, acc[3][1]);
        }
        __syncthreads();
    }

    // ---- epilogue: normalize + store (4 rows x 4 feats) ----
#pragma unroll
    for (int i = 0; i < 4; i++) {
        int r = rg * 4 + i;
        int n = n0 + r;
        if (n >= N_NODES) continue;
        float inv = invs[r];
        float2 f0 = upk2(acc[i][0]);
        float2 f1 = upk2(acc[i][1]);
        float* dst = out + (size_t)n * (M_MECH * OUTS) + m * 64 + fg * 4;
        *(float4*)dst = make_float4(f0.x * inv, f0.y * inv, f1.x * inv, f1.y * inv);
    }
}

// ---------------- launch ----------------
extern "C" void kernel_launch(void* const* d_in, const int* in_sizes, int n_in,
                              void* d_out, int out_size) {
    const float*    x     = (const float*)d_in[0];
    const unsigned* adj   = (const unsigned*)d_in[1];
    const float*    W     = (const float*)d_in[2];
    const float*    a_src = (const float*)d_in[3];
    const float*    a_dst = (const float*)d_in[4];
    const float*    Wc1   = (const float*)d_in[5];
    const float*    bc1   = (const float*)d_in[6];
    const float*    Wc2   = (const float*)d_in[7];
    const float*    bc2   = (const float*)d_in[8];
    float* out = (float*)d_out;

    k_pack<<<N_NODES, 128>>>(adj);
    k_gemm<<<dim3(43, 9), 256>>>(x, W, Wc1, bc1);
    k_cond_film<<<339, 256>>>(Wc2, bc2, a_src, a_dst);
    k_attn<<<dim3((N_NODES + AR - 1) / AR, M_MECH), 256>>>(out);
}

// round 10
// speedup vs baseline: 2.4022x; 1.0734x over previous
#include <cuda_runtime.h>
#include <cstdint>

#define N_NODES 2708
#define INS     1433
#define OUTS    64
#define M_MECH  8
#define HID     64
#define LEAK    0.2f
#define NW      85   // ceil(2708/32)
#define NCH     90   // ceil(1433/16)

typedef unsigned long long ull;

// ---------------- device scratch (no allocation allowed) ----------------
__device__ unsigned g_adj[N_NODES * NW];
__device__ float g_h[(size_t)M_MECH * N_NODES * OUTS];   // raw then FiLM'd projections
__device__ float g_h1[(size_t)N_NODES * HID];            // conditioner hidden
__device__ float g_es[M_MECH * N_NODES];
__device__ float g_ed[M_MECH * N_NODES];
__device__ float g_maxed[M_MECH];

// ---------------- f32x2 helpers (sm_103a packed FP32) ----------------
__device__ __forceinline__ ull pk2(float a, float b) {
    ull r; asm("mov.b64 %0, {%1, %2};" : "=l"(r) : "f"(a), "f"(b)); return r;
}
__device__ __forceinline__ float2 upk2(ull v) {
    float2 r; asm("mov.b64 {%0, %1}, %2;" : "=f"(r.x), "=f"(r.y) : "l"(v)); return r;
}
__device__ __forceinline__ ull ffma2(ull a, ull b, ull c) {
    ull d; asm("fma.rn.f32x2 %0, %1, %2, %3;" : "=l"(d) : "l"(a), "l"(b), "l"(c)); return d;
}

// ---------------- K1: bit-pack adjacency ----------------
__global__ void k_pack(const unsigned* __restrict__ adj) {
    int i = blockIdx.x;
    int lane = threadIdx.x & 31, w0 = threadIdx.x >> 5;
    for (int w = w0; w < NW; w += 4) {
        int j = w * 32 + lane;
        bool p = (j < N_NODES) && (adj[(size_t)i * N_NODES + j] != 0u);
        unsigned mask = __ballot_sync(0xFFFFFFFFu, p);
        if (lane == 0) g_adj[i * NW + w] = mask;
    }
}

// ---------------- K2: fused big GEMM, double-buffered, dup-packed A ----------------
__global__ void k_gemm(const float* __restrict__ x, const float* __restrict__ W,
                       const float* __restrict__ Wc1, const float* __restrict__ bc1) {
    __shared__ __align__(16) float2 xs[2][16][66];  // xs[b][k][row] = (v,v) duplicated
    __shared__ __align__(16) float  bs[2][16][64];  // bs[b][k][col]

    int n0 = blockIdx.x * 64;
    int gy = blockIdx.y;
    const float* B = (gy < M_MECH) ? (W + (size_t)gy * INS * OUTS) : Wc1;

    int t = threadIdx.x;
    int trow = t >> 4, tcol = t & 15;

    int xr[4], xk[4], bk[4], bo[4];
#pragma unroll
    for (int i = 0; i < 4; i++) {
        int e = t + 256 * i;
        xr[i] = e >> 4;  xk[i] = e & 15;
        bk[i] = e >> 6;  bo[i] = e & 63;
    }

    ull acc[8];
#pragma unroll
    for (int i = 0; i < 8; i++) acc[i] = 0ull;

    float rx[4], rb[4];
#pragma unroll
    for (int i = 0; i < 4; i++) {
        int gr = n0 + xr[i], gk = xk[i];
        rx[i] = (gr < N_NODES && gk < INS) ? x[(size_t)gr * INS + gk] : 0.f;
        rb[i] = (bk[i] < INS) ? B[(size_t)bk[i] * 64 + bo[i]] : 0.f;
    }
#pragma unroll
    for (int i = 0; i < 4; i++) {
        xs[0][xk[i]][xr[i]] = make_float2(rx[i], rx[i]);
        bs[0][bk[i]][bo[i]] = rb[i];
    }
    __syncthreads();

    for (int c = 0; c < NCH; c++) {
        int k0n = (c + 1) * 16;
        if (c + 1 < NCH) {
#pragma unroll
            for (int i = 0; i < 4; i++) {
                int gr = n0 + xr[i], gk = k0n + xk[i];
                rx[i] = (gr < N_NODES && gk < INS) ? x[(size_t)gr * INS + gk] : 0.f;
                int gkb = k0n + bk[i];
                rb[i] = (gkb < INS) ? B[(size_t)gkb * 64 + bo[i]] : 0.f;
            }
        }
        int cb = c & 1;
#pragma unroll
        for (int kk = 0; kk < 16; kk++) {
            // 4 dup-pairs of A (rows), 2 natural pairs of B (cols) — no movs
            ulonglong2 qa = *(const ulonglong2*)&xs[cb][kk][trow * 4];
            ulonglong2 qb = *(const ulonglong2*)&xs[cb][kk][trow * 4 + 2];
            ulonglong2 p  = *(const ulonglong2*)&bs[cb][kk][tcol * 4];
            acc[0] = ffma2(qa.x, p.x, acc[0]);
            acc[1] = ffma2(qa.x, p.y, acc[1]);
            acc[2] = ffma2(qa.y, p.x, acc[2]);
            acc[3] = ffma2(qa.y, p.y, acc[3]);
            acc[4] = ffma2(qb.x, p.x, acc[4]);
            acc[5] = ffma2(qb.x, p.y, acc[5]);
            acc[6] = ffma2(qb.y, p.x, acc[6]);
            acc[7] = ffma2(qb.y, p.y, acc[7]);
        }
        if (c + 1 < NCH) {
            int nb = cb ^ 1;
#pragma unroll
            for (int i = 0; i < 4; i++) {
                xs[nb][xk[i]][xr[i]] = make_float2(rx[i], rx[i]);
                bs[nb][bk[i]][bo[i]] = rb[i];
            }
        }
        __syncthreads();
    }

#pragma unroll
    for (int i = 0; i < 4; i++) {
        int n = n0 + trow * 4 + i;
        if (n >= N_NODES) continue;
        float2 c01 = upk2(acc[i * 2]);
        float2 c23 = upk2(acc[i * 2 + 1]);
        int oc = tcol * 4;
        if (gy < M_MECH) {
            float4 v = make_float4(c01.x, c01.y, c23.x, c23.y);
            *(float4*)&g_h[((size_t)gy * N_NODES + n) * 64 + oc] = v;
        } else {
            float4 v = make_float4(fmaxf(c01.x + bc1[oc], 0.f),
                                   fmaxf(c01.y + bc1[oc + 1], 0.f),
                                   fmaxf(c23.x + bc1[oc + 2], 0.f),
                                   fmaxf(c23.y + bc1[oc + 3], 0.f));
            *(float4*)&g_h1[(size_t)n * 64 + oc] = v;
        }
    }
}

// ---------------- K3: conditioner out + FiLM + e_src/e_dst, fused ----------------
__global__ void k_cond_film(const float* __restrict__ Wc2, const float* __restrict__ bc2,
                            const float* __restrict__ a_src, const float* __restrict__ a_dst) {
    int n = blockIdx.x * 8 + (threadIdx.x >> 5);
    int lane = threadIdx.x & 31;
    if (n >= N_NODES) return;

    float v0 = g_h1[(size_t)n * 64 + lane];
    float v1 = g_h1[(size_t)n * 64 + 32 + lane];
    float s = (lane < 16) ? bc2[lane] : 0.f;
#pragma unroll
    for (int k = 0; k < 64; k++) {
        float hv = __shfl_sync(0xFFFFFFFFu, (k < 32) ? v0 : v1, k & 31);
        float w = (lane < 16) ? Wc2[k * 16 + lane] : 0.f;
        s = fmaf(hv, w, s);
    }
#pragma unroll
    for (int m = 0; m < M_MECH; m++) {
        float g = __shfl_sync(0xFFFFFFFFu, s, m);
        float b = __shfl_sync(0xFFFFFFFFu, s, m + 8);
        size_t base = ((size_t)m * N_NODES + n) * 64;
        float h0 = g_h[base + lane], h1 = g_h[base + 32 + lane];
        h0 = fmaf(g, h0, b);
        h1 = fmaf(g, h1, b);
        g_h[base + lane] = h0;
        g_h[base + 32 + lane] = h1;
        float es = h0 * a_src[m * 64 + lane] + h1 * a_src[m * 64 + 32 + lane];
        float ed = h0 * a_dst[m * 64 + lane] + h1 * a_dst[m * 64 + 32 + lane];
#pragma unroll
        for (int off = 16; off; off >>= 1) {
            es += __shfl_xor_sync(0xFFFFFFFFu, es, off);
            ed += __shfl_xor_sync(0xFFFFFFFFu, ed, off);
        }
        if (lane == 0) { g_es[m * N_NODES + n] = es; g_ed[m * N_NODES + n] = ed; }
    }
}

// ---------------- K3b: global max of ed per mechanism (softmax stabilizer) ----------------
__global__ void k_maxed() {
    __shared__ float red[8];
    int m = blockIdx.x;
    int t = threadIdx.x, lane = t & 31, wid = t >> 5;
    float mx = -1e30f;
    for (int j = t; j < N_NODES; j += 256) mx = fmaxf(mx, g_ed[m * N_NODES + j]);
#pragma unroll
    for (int off = 16; off; off >>= 1)
        mx = fmaxf(mx, __shfl_xor_sync(0xFFFFFFFFu, mx, off));
    if (lane == 0) red[wid] = mx;
    __syncthreads();
    if (t == 0) {
        float r = red[0];
#pragma unroll
        for (int i = 1; i < 8; i++) r = fmaxf(r, red[i]);
        g_maxed[m] = r;
    }
}

// ---------------- K4: fused masked softmax + aggregation (single sweep) ----------------
// block = (m, 64-row tile), 256 threads. Thread tile: 4 rows x 4 feats.
// Weights pre-duplicated in smem -> inner loop is 3 LDS.128 + 8 FFMA2, no movs.
// Row max analytic: leaky monotonic => mx_r = leaky(es[r] + max_j ed[j]).
// Softmax denominator accumulated inline, normalization in epilogue.
#define AR   64
#define TJ   32

__global__ void __launch_bounds__(256, 4) k_attn(float* __restrict__ out) {
    __shared__ __align__(16) float2 wsd[TJ][64];   // duplicated weights [jj][row] (16KB)
    __shared__ __align__(16) float  hs[TJ][64];    // h tile [jj][feat]        (8KB)
    __shared__ float es_s[AR];
    __shared__ float psum[AR][4];
    __shared__ float invs[AR];

    int m = blockIdx.y;
    int n0 = blockIdx.x * AR;
    int t = threadIdx.x;
    int rr_w = t & 63, ib = t >> 6;    // weight-gen coords: row rr_w, jl subset ib+4i
    int rg = t >> 4, fg = t & 15;      // mainloop coords: rows rg*4.., feats fg*4..

    if (t < AR) {
        int n = n0 + t;
        es_s[t] = (n < N_NODES) ? g_es[m * N_NODES + n] : 0.f;
    }
    __syncthreads();

    float maxed = g_maxed[m];
    float esr = es_s[rr_w];
    float vmx = esr + maxed;
    vmx = (vmx > 0.f) ? vmx : LEAK * vmx;          // row max (analytic)
    int nrow = n0 + rr_w;
    const unsigned* arow = g_adj + (size_t)nrow * NW;
    const float* edp = g_ed + (size_t)m * N_NODES;
    float rsum = 0.f;

    ull acc[4][2];
#pragma unroll
    for (int i = 0; i < 4; i++) { acc[i][0] = 0ull; acc[i][1] = 0ull; }

    for (int jt = 0; jt < N_NODES; jt += TJ) {
        // stage h tile [TJ x 64]
        const float* hsrc = g_h + ((size_t)m * N_NODES + jt) * 64;
        int jrem = N_NODES - jt;
#pragma unroll
        for (int i = 0; i < 2; i++) {
            int e4 = t + 256 * i;
            int jj = e4 >> 4, oc = (e4 & 15) * 4;
            float4 v = (jj < jrem) ? *(const float4*)&hsrc[(size_t)jj * 64 + oc]
                                   : make_float4(0.f, 0.f, 0.f, 0.f);
            *(float4*)&hs[jj][oc] = v;
        }
        // weights: one adjacency word per (row, tile); exp once per edge
        unsigned word = (nrow < N_NODES) ? arow[jt >> 5] : 0u;
#pragma unroll
        for (int i = 0; i < 8; i++) {
            int jl = ib + 4 * i;
            int j = jt + jl;
            float w = 0.f;
            if (j < N_NODES && ((word >> jl) & 1u)) {
                float v = esr + edp[j];
                v = (v > 0.f) ? v : LEAK * v;
                w = __expf(v - vmx);
            }
            wsd[jl][rr_w] = make_float2(w, w);
            rsum += w;
        }
        __syncthreads();

        // mainloop: 3 LDS.128 + 8 FFMA2 per jj, zero movs
        const float2* wp = &wsd[0][rg * 4];
        const ull*    hp = (const ull*)&hs[0][fg * 4];
#pragma unroll 8
        for (int jj = 0; jj < TJ; jj++) {
            ulonglong2 qa = *(const ulonglong2*)(wp + (size_t)jj * 64);
            ulonglong2 qb = *(const ulonglong2*)(wp + (size_t)jj * 64 + 2);
            ulonglong2 p  = *(const ulonglong2*)(hp + (size_t)jj * 32);
            acc[0][0] = ffma2(qa.x, p.x, acc[0][0]);
            acc[0][1] = ffma2(qa.x, p.y, acc[0][1]);
            acc[1][0] = ffma2(qa.y, p.x, acc[1][0]);
            acc[1][1] = ffma2(qa.y, p.y, acc[1][1]);
            acc[2][0] = ffma2(qb.x, p.x, acc[2][0]);
            acc[2][1] = ffma2(qb.x, p.y, acc[2][1]);
            acc[3][0] = ffma2(qb.y, p.x, acc[3][0]);
            acc[3][1] = ffma2(qb.y, p.y, acc[3][1]);
        }
        __syncthreads();
    }

    // denominator: combine 4 partials per row
    psum[rr_w][ib] = rsum;
    __syncthreads();
    if (t < AR) {
        float S = psum[t][0] + psum[t][1] + psum[t][2] + psum[t][3];
        invs[t] = (S > 0.f) ? 1.f / S : 0.f;
    }
    __syncthreads();

    // epilogue: normalize + store (4 rows x 4 feats)
#pragma unroll
    for (int i = 0; i < 4; i++) {
        int r = rg * 4 + i;
        int n = n0 + r;
        if (n >= N_NODES) continue;
        float inv = invs[r];
        float2 f0 = upk2(acc[i][0]);
        float2 f1 = upk2(acc[i][1]);
        float* dst = out + (size_t)n * (M_MECH * OUTS) + m * 64 + fg * 4;
        *(float4*)dst = make_float4(f0.x * inv, f0.y * inv, f1.x * inv, f1.y * inv);
    }
}

// ---------------- launch ----------------
extern "C" void kernel_launch(void* const* d_in, const int* in_sizes, int n_in,
                              void* d_out, int out_size) {
    const float*    x     = (const float*)d_in[0];
    const unsigned* adj   = (const unsigned*)d_in[1];
    const float*    W     = (const float*)d_in[2];
    const float*    a_src = (const float*)d_in[3];
    const float*    a_dst = (const float*)d_in[4];
    const float*    Wc1   = (const float*)d_in[5];
    const float*    bc1   = (const float*)d_in[6];
    const float*    Wc2   = (const float*)d_in[7];
    const float*    bc2   = (const float*)d_in[8];
    float* out = (float*)d_out;

    k_pack<<<N_NODES, 128>>>(adj);
    k_gemm<<<dim3(43, 9), 256>>>(x, W, Wc1, bc1);
    k_cond_film<<<339, 256>>>(Wc2, bc2, a_src, a_dst);
    k_maxed<<<M_MECH, 256>>>();
    k_attn<<<dim3((N_NODES + AR - 1) / AR, M_MECH), 256>>>(out);
}